// round 4
// baseline (speedup 1.0000x reference)
#include <cuda_runtime.h>
#include <cuda_bf16.h>
#include <math.h>

#define Bn     64
#define Vn     16384
#define En     524288
#define Kc     6
#define F1     32
#define POOLn  8
#define VG     (Vn / POOLn)       // 2048
#define FC1FIN (F1 * VG)          // 65536
#define FC1F   512
#define FC2F   512
#define NN1F   1024
#define NN2F   512
#define OUTC   10

// ---------------- scratch (device globals; no runtime allocation) ----------
__device__ __align__(16) float g_xs[6 * Vn * Bn];        // Chebyshev basis, [k][v][b]
__device__ __align__(16) float g_pooled[FC1FIN * Bn];    // [i][b]
__device__ __align__(16) float g_yfc1[FC1F * Bn];
__device__ __align__(16) float g_hid[FC1F * Bn];
__device__ __align__(16) float g_yfc2[FC2F * Bn];
__device__ __align__(16) float g_xd[FC2F * Bn];
__device__ __align__(16) float g_yfc3[Vn * Bn];
__device__ __align__(16) float g_ynn1[NN1F * Bn];
__device__ __align__(16) float g_xn1[NN1F * Bn];
__device__ __align__(16) float g_ynn2[NN2F * Bn];
__device__ __align__(16) float g_xn2[NN2F * Bn];
__device__ int  g_rowptr[Vn + 1];
__device__ int  g_cursor[Vn];
__device__ __align__(8) int2 g_csr[En];                  // (col, val bits)

// ---------------- transpose x_in [64][V] -> [V][64] ------------------------
__global__ void k_transpose_in(const float* __restrict__ xin, float* __restrict__ xout) {
    __shared__ float t[32][33];
    int v0 = blockIdx.x * 32, b0 = blockIdx.y * 32;
    int tx = threadIdx.x, ty = threadIdx.y;
    #pragma unroll
    for (int j = 0; j < 32; j += 8)
        t[ty + j][tx] = xin[(size_t)(b0 + ty + j) * Vn + v0 + tx];
    __syncthreads();
    #pragma unroll
    for (int j = 0; j < 32; j += 8)
        xout[(size_t)(v0 + ty + j) * Bn + b0 + tx] = t[tx][ty + j];
}

// ---------------- CSR build -------------------------------------------------
__global__ void k_hist(const int* __restrict__ rows) {
    int e = blockIdx.x * 256 + threadIdx.x;
    if (e < En) atomicAdd(&g_rowptr[rows[e] + 1], 1);
}

__global__ void k_scan() {   // 1 block, 1024 threads, V = 1024*16
    __shared__ int sm[1024];
    int tid = threadIdx.x;
    int loc[16];
    int base = 1 + tid * 16;
    int s = 0;
    #pragma unroll
    for (int j = 0; j < 16; j++) { loc[j] = g_rowptr[base + j]; s += loc[j]; }
    sm[tid] = s;
    __syncthreads();
    for (int off = 1; off < 1024; off <<= 1) {
        int v = (tid >= off) ? sm[tid - off] : 0;
        __syncthreads();
        sm[tid] += v;
        __syncthreads();
    }
    int run = sm[tid] - s;   // exclusive prefix of this thread's chunk
    #pragma unroll
    for (int j = 0; j < 16; j++) { run += loc[j]; g_rowptr[base + j] = run; }
}

__global__ void k_scatter(const int* __restrict__ rows, const int* __restrict__ cols,
                          const float* __restrict__ vals) {
    int e = blockIdx.x * 256 + threadIdx.x;
    if (e < En) {
        int r = rows[e];
        int p = g_rowptr[r] + atomicAdd(&g_cursor[r], 1);
        g_csr[p] = make_int2(cols[e], __float_as_int(vals[e]));
    }
}

// ---------------- SpMM: out = alpha * (L @ x) + beta * prev ----------------
// warp per row; lane handles 2 batch columns (float2)
__global__ void k_spmm(const float* __restrict__ xin, const float* __restrict__ prev,
                       float* __restrict__ xout, float alpha, float beta) {
    int warp = threadIdx.x >> 5, lane = threadIdx.x & 31;
    int row = blockIdx.x * 8 + warp;
    int s = g_rowptr[row], e = g_rowptr[row + 1];
    const float2* __restrict__ xin2 = (const float2*)xin;
    float2 acc = make_float2(0.f, 0.f);
    int i = s;
    for (; i + 1 < e; i += 2) {
        int2 cv0 = g_csr[i];
        int2 cv1 = g_csr[i + 1];
        float2 x0 = xin2[(size_t)cv0.x * 32 + lane];
        float2 x1 = xin2[(size_t)cv1.x * 32 + lane];
        float v0 = __int_as_float(cv0.y), v1 = __int_as_float(cv1.y);
        acc.x += v0 * x0.x; acc.y += v0 * x0.y;
        acc.x += v1 * x1.x; acc.y += v1 * x1.y;
    }
    if (i < e) {
        int2 cv = g_csr[i];
        float2 xv = xin2[(size_t)cv.x * 32 + lane];
        float v = __int_as_float(cv.y);
        acc.x += v * xv.x; acc.y += v * xv.y;
    }
    size_t o = (size_t)row * 32 + lane;
    float2 pv = ((const float2*)prev)[o];
    float2 r;
    r.x = alpha * acc.x + beta * pv.x;
    r.y = alpha * acc.y + beta * pv.y;
    ((float2*)xout)[o] = r;
}

// ---------------- fused cheby-combine + relu + maxpool ----------------------
// block (64,4): x = batch, y = local vgroup; writes pooled[(vg*32+f)][b]
__global__ void k_chebypool(const float* __restrict__ w, const float* __restrict__ bias) {
    __shared__ float sw[F1 * Kc];
    __shared__ float sb[F1];
    int tid = threadIdx.y * 64 + threadIdx.x;
    if (tid < F1 * Kc) sw[tid] = w[tid];
    if (tid >= F1 * Kc && tid < F1 * Kc + F1) sb[tid - F1 * Kc] = bias[tid - F1 * Kc];
    __syncthreads();
    int b  = threadIdx.x;
    int vg = blockIdx.x * 4 + threadIdx.y;
    float mx[F1];
    #pragma unroll
    for (int f = 0; f < F1; f++) mx[f] = -INFINITY;
    int v0 = vg * POOLn;
    for (int v = v0; v < v0 + POOLn; v++) {
        float t[Kc];
        #pragma unroll
        for (int k = 0; k < Kc; k++)
            t[k] = g_xs[(size_t)k * Vn * Bn + (size_t)v * Bn + b];
        #pragma unroll
        for (int f = 0; f < F1; f++) {
            float s = sb[f];
            #pragma unroll
            for (int k = 0; k < Kc; k++) s += t[k] * sw[f * Kc + k];
            mx[f] = fmaxf(mx[f], s);
        }
    }
    #pragma unroll
    for (int f = 0; f < F1; f++)
        g_pooled[((size_t)vg * F1 + f) * Bn + b] = fmaxf(mx[f], 0.f);
}

// ---------------- generic fp32 GEMM: Y[n][b] += sum_k X[k][b]*W[n][k] -------
// grid (N/64, S), block 256; split-K partials accumulated with atomicAdd.
__global__ __launch_bounds__(256)
void k_gemm(const float* __restrict__ X, const float* __restrict__ W,
            float* __restrict__ Y, int N, int K, int kspan) {
    const int KC = 32;
    __shared__ __align__(16) float Xs[KC * 64];
    __shared__ __align__(16) float Ws[KC][68];
    int tid = threadIdx.x;
    int n0 = blockIdx.x * 64;
    int k0 = blockIdx.y * kspan;
    int k1 = min(K, k0 + kspan);
    int bg = tid & 15;          // b = bg*4
    int ng = tid >> 4;          // n = ng*4
    float a00=0,a01=0,a02=0,a03=0, a10=0,a11=0,a12=0,a13=0;
    float a20=0,a21=0,a22=0,a23=0, a30=0,a31=0,a32=0,a33=0;
    // W-tile loader geometry: 64 rows x 8 float4-groups = 512 float4, 2/thread
    int wrow = tid >> 2;            // 0..63
    int wj0  = (tid & 3) * 4;       // k-offset 0,4,8,12 (second pass +16)
    for (int kb = k0; kb < k1; kb += KC) {
        __syncthreads();
        {   // X chunk: contiguous 8KB, 512 float4, 2/thread
            const float4* Xg = (const float4*)(X + (size_t)kb * 64);
            float4* Xs4 = (float4*)Xs;
            Xs4[tid]       = Xg[tid];
            Xs4[tid + 256] = Xg[tid + 256];
        }
        {   // W chunk: 64 rows x 32 k, store transposed [k][n]
            #pragma unroll
            for (int h = 0; h < 2; h++) {
                int jj = wj0 + h * 16;
                float4 wv = *(const float4*)(W + (size_t)(n0 + wrow) * K + kb + jj);
                Ws[jj + 0][wrow] = wv.x;
                Ws[jj + 1][wrow] = wv.y;
                Ws[jj + 2][wrow] = wv.z;
                Ws[jj + 3][wrow] = wv.w;
            }
        }
        __syncthreads();
        #pragma unroll
        for (int k = 0; k < KC; k++) {
            float4 xv = *(const float4*)(Xs + k * 64 + bg * 4);
            float4 wv = *(const float4*)(&Ws[k][ng * 4]);
            a00 += wv.x * xv.x; a01 += wv.x * xv.y; a02 += wv.x * xv.z; a03 += wv.x * xv.w;
            a10 += wv.y * xv.x; a11 += wv.y * xv.y; a12 += wv.y * xv.z; a13 += wv.y * xv.w;
            a20 += wv.z * xv.x; a21 += wv.z * xv.y; a22 += wv.z * xv.z; a23 += wv.z * xv.w;
            a30 += wv.w * xv.x; a31 += wv.w * xv.y; a32 += wv.w * xv.z; a33 += wv.w * xv.w;
        }
    }
    float* y = Y + (size_t)(n0 + ng * 4) * 64 + bg * 4;
    atomicAdd(y + 0*64 + 0, a00); atomicAdd(y + 0*64 + 1, a01); atomicAdd(y + 0*64 + 2, a02); atomicAdd(y + 0*64 + 3, a03);
    atomicAdd(y + 1*64 + 0, a10); atomicAdd(y + 1*64 + 1, a11); atomicAdd(y + 1*64 + 2, a12); atomicAdd(y + 1*64 + 3, a13);
    atomicAdd(y + 2*64 + 0, a20); atomicAdd(y + 2*64 + 1, a21); atomicAdd(y + 2*64 + 2, a22); atomicAdd(y + 2*64 + 3, a23);
    atomicAdd(y + 3*64 + 0, a30); atomicAdd(y + 3*64 + 1, a31); atomicAdd(y + 3*64 + 2, a32); atomicAdd(y + 3*64 + 3, a33);
}

// ---------------- epilogues -------------------------------------------------
__global__ void k_bias_act(const float* __restrict__ Y, const float* __restrict__ bias,
                           float* __restrict__ dst, int total, int relu) {
    int i = blockIdx.x * 256 + threadIdx.x;
    if (i < total) {
        int n = i >> 6;
        float v = Y[i] + bias[n];
        if (relu) v = fmaxf(v, 0.f);
        dst[i] = v;
    }
}

__global__ void k_copy_hidden(const float* __restrict__ hid, float* __restrict__ out2) {
    int i = blockIdx.x * 256 + threadIdx.x;
    if (i < FC1F * Bn) {
        int n = i >> 6, b = i & 63;
        out2[b * FC1F + n] = hid[i];
    }
}

// fc3 epilogue: add bias + transpose [v][b] -> out[b][v]
__global__ void k_fc3_out(const float* __restrict__ Y, const float* __restrict__ bias,
                          float* __restrict__ out) {
    __shared__ float t[32][33];
    int v0 = blockIdx.x * 32, b0 = blockIdx.y * 32;
    int tx = threadIdx.x, ty = threadIdx.y;
    #pragma unroll
    for (int j = 0; j < 32; j += 8)
        t[ty + j][tx] = Y[(size_t)(v0 + ty + j) * 64 + b0 + tx] + bias[v0 + ty + j];
    __syncthreads();
    #pragma unroll
    for (int j = 0; j < 32; j += 8)
        out[(size_t)(b0 + ty + j) * Vn + v0 + tx] = t[tx][ty + j];
}

// ---------------- fused sum2 + log_softmax ----------------------------------
__global__ void k_sum2(const float* __restrict__ hid, const float* __restrict__ xn2,
                       const float* __restrict__ w, const float* __restrict__ bias,
                       float* __restrict__ outlp) {
    int b = blockIdx.x, tid = threadIdx.x;
    float acc[OUTC];
    #pragma unroll
    for (int n = 0; n < OUTC; n++) acc[n] = 0.f;
    for (int k = tid; k < FC1F + NN2F; k += 256) {
        float xv = (k < FC1F) ? hid[k * 64 + b] : xn2[(k - FC1F) * 64 + b];
        #pragma unroll
        for (int n = 0; n < OUTC; n++) acc[n] += xv * w[n * (FC1F + NN2F) + k];
    }
    #pragma unroll
    for (int off = 16; off; off >>= 1)
        #pragma unroll
        for (int n = 0; n < OUTC; n++)
            acc[n] += __shfl_down_sync(0xffffffffu, acc[n], off);
    __shared__ float red[8][OUTC];
    int lane = tid & 31, wp = tid >> 5;
    if (lane == 0)
        #pragma unroll
        for (int n = 0; n < OUTC; n++) red[wp][n] = acc[n];
    __syncthreads();
    if (tid == 0) {
        float z[OUTC];
        #pragma unroll
        for (int n = 0; n < OUTC; n++) {
            float s = bias[n];
            #pragma unroll
            for (int w8 = 0; w8 < 8; w8++) s += red[w8][n];
            z[n] = s;
        }
        float m = z[0];
        #pragma unroll
        for (int n = 1; n < OUTC; n++) m = fmaxf(m, z[n]);
        float se = 0.f;
        #pragma unroll
        for (int n = 0; n < OUTC; n++) se += expf(z[n] - m);
        float l = m + logf(se);
        #pragma unroll
        for (int n = 0; n < OUTC; n++) outlp[b * OUTC + n] = z[n] - l;
    }
}

// ---------------- launcher --------------------------------------------------
extern "C" void kernel_launch(void* const* d_in, const int* in_sizes, int n_in,
                              void* d_out, int out_size) {
    const float* x_in   = (const float*)d_in[0];
    const float* L_vals = (const float*)d_in[1];
    const float* cl1_w  = (const float*)d_in[2];
    const float* cl1_b  = (const float*)d_in[3];
    const float* fc1_w  = (const float*)d_in[4];
    const float* fc1_b  = (const float*)d_in[5];
    const float* fc2_w  = (const float*)d_in[6];
    const float* fc2_b  = (const float*)d_in[7];
    const float* fc3_w  = (const float*)d_in[8];
    const float* fc3_b  = (const float*)d_in[9];
    const float* nn1_w  = (const float*)d_in[10];
    const float* nn1_b  = (const float*)d_in[11];
    const float* nn2_w  = (const float*)d_in[12];
    const float* nn2_b  = (const float*)d_in[13];
    const float* sum2_w = (const float*)d_in[14];
    const float* sum2_b = (const float*)d_in[15];
    const int*   L_rows = (const int*)d_in[16];
    const int*   L_cols = (const int*)d_in[17];

    float* out = (float*)d_out;
    float* out_dec = out;                       // [64][16384]
    float* out_hid = out + (size_t)Bn * Vn;     // [64][512]
    float* out_lp  = out_hid + Bn * FC1F;       // [64][10]

    void *p_xs, *p_pooled, *p_yfc1, *p_hid, *p_yfc2, *p_xd, *p_yfc3;
    void *p_ynn1, *p_xn1, *p_ynn2, *p_xn2, *p_rowptr, *p_cursor;
    cudaGetSymbolAddress(&p_xs, g_xs);
    cudaGetSymbolAddress(&p_pooled, g_pooled);
    cudaGetSymbolAddress(&p_yfc1, g_yfc1);
    cudaGetSymbolAddress(&p_hid, g_hid);
    cudaGetSymbolAddress(&p_yfc2, g_yfc2);
    cudaGetSymbolAddress(&p_xd, g_xd);
    cudaGetSymbolAddress(&p_yfc3, g_yfc3);
    cudaGetSymbolAddress(&p_ynn1, g_ynn1);
    cudaGetSymbolAddress(&p_xn1, g_xn1);
    cudaGetSymbolAddress(&p_ynn2, g_ynn2);
    cudaGetSymbolAddress(&p_xn2, g_xn2);
    cudaGetSymbolAddress(&p_rowptr, g_rowptr);
    cudaGetSymbolAddress(&p_cursor, g_cursor);

    float* xs     = (float*)p_xs;
    float* pooled = (float*)p_pooled;
    const size_t VB = (size_t)Vn * Bn;

    // CSR build + input transpose
    cudaMemsetAsync(p_rowptr, 0, (Vn + 1) * sizeof(int));
    cudaMemsetAsync(p_cursor, 0, Vn * sizeof(int));
    k_transpose_in<<<dim3(Vn / 32, Bn / 32), dim3(32, 8)>>>(x_in, xs);
    k_hist<<<En / 256, 256>>>(L_rows);
    k_scan<<<1, 1024>>>();
    k_scatter<<<En / 256, 256>>>(L_rows, L_cols, L_vals);

    // Chebyshev recursion: xs[k] = 2 L xs[k-1] - xs[k-2]
    k_spmm<<<Vn / 8, 256>>>(xs,          xs,          xs + VB,     1.f,  0.f);
    k_spmm<<<Vn / 8, 256>>>(xs + VB,     xs,          xs + 2 * VB, 2.f, -1.f);
    k_spmm<<<Vn / 8, 256>>>(xs + 2 * VB, xs + VB,     xs + 3 * VB, 2.f, -1.f);
    k_spmm<<<Vn / 8, 256>>>(xs + 3 * VB, xs + 2 * VB, xs + 4 * VB, 2.f, -1.f);
    k_spmm<<<Vn / 8, 256>>>(xs + 4 * VB, xs + 3 * VB, xs + 5 * VB, 2.f, -1.f);

    // combine + relu + maxpool -> pooled [65536][64]
    k_chebypool<<<VG / 4, dim3(64, 4)>>>(cl1_w, cl1_b);

    // fc1 -> hidden
    cudaMemsetAsync(p_yfc1, 0, (size_t)FC1F * Bn * sizeof(float));
    k_gemm<<<dim3(FC1F / 64, 64), 256>>>(pooled, fc1_w, (float*)p_yfc1, FC1F, FC1FIN, 1024);
    k_bias_act<<<(FC1F * Bn + 255) / 256, 256>>>((float*)p_yfc1, fc1_b, (float*)p_hid, FC1F * Bn, 1);
    k_copy_hidden<<<(FC1F * Bn + 255) / 256, 256>>>((float*)p_hid, out_hid);

    // nn branch (input = x_in^T = xs[0])
    cudaMemsetAsync(p_ynn1, 0, (size_t)NN1F * Bn * sizeof(float));
    k_gemm<<<dim3(NN1F / 64, 16), 256>>>(xs, nn1_w, (float*)p_ynn1, NN1F, Vn, 1024);
    k_bias_act<<<(NN1F * Bn + 255) / 256, 256>>>((float*)p_ynn1, nn1_b, (float*)p_xn1, NN1F * Bn, 1);
    cudaMemsetAsync(p_ynn2, 0, (size_t)NN2F * Bn * sizeof(float));
    k_gemm<<<dim3(NN2F / 64, 4), 256>>>((float*)p_xn1, nn2_w, (float*)p_ynn2, NN2F, NN1F, 256);
    k_bias_act<<<(NN2F * Bn + 255) / 256, 256>>>((float*)p_ynn2, nn2_b, (float*)p_xn2, NN2F * Bn, 1);

    // decode branch
    cudaMemsetAsync(p_yfc2, 0, (size_t)FC2F * Bn * sizeof(float));
    k_gemm<<<dim3(FC2F / 64, 4), 256>>>((float*)p_hid, fc2_w, (float*)p_yfc2, FC2F, FC1F, 128);
    k_bias_act<<<(FC2F * Bn + 255) / 256, 256>>>((float*)p_yfc2, fc2_b, (float*)p_xd, FC2F * Bn, 1);
    cudaMemsetAsync(p_yfc3, 0, (size_t)Vn * Bn * sizeof(float));
    k_gemm<<<dim3(Vn / 64, 1), 256>>>((float*)p_xd, fc3_w, (float*)p_yfc3, Vn, FC2F, 512);
    k_fc3_out<<<dim3(Vn / 32, Bn / 32), dim3(32, 8)>>>((float*)p_yfc3, fc3_b, out_dec);

    // classifier head
    k_sum2<<<Bn, 256>>>((float*)p_hid, (float*)p_xn2, sum2_w, sum2_b, out_lp);
}